// round 13
// baseline (speedup 1.0000x reference)
#include <cuda_runtime.h>

#define NN 8192
#define INDIM 512
#define HID 50
#define ZD 128
#define NCAT 64
#define EPSV 1e-8f
#define NWORK_MAX (NN/32 + NCAT)
#define NFX (NN/32)
#define NFZ (NN/32)

// uneg dynamic smem layout (floats):
//  phase1: FxsTd [128][68] = 8704   | Wst [32][132] = 4224   (total 12928)
//  phase2: Us    [32][128] = 4096   | Fs  [64][132] = 8448   (total 12544)
#define UNEG_SMEM_FLOATS 12928
#define UNEG_SMEM_BYTES  (UNEG_SMEM_FLOATS*4)

typedef unsigned long long u64;

// ---------------- scratch ----------------------------------------------------
__device__ float g_fx[NN*ZD];    // natural order
__device__ float g_fz[NN*ZD];    // natural order
__device__ int   g_cnt[NCAT], g_start[NCAT];
__device__ int   g_sorted[NN];
__device__ int   g_work[NWORK_MAX];
__device__ int   g_nwork;

// ---------------- f32x2 helpers ----------------------------------------------
__device__ __forceinline__ u64 dup2(float x){
    u64 r; asm("mov.b64 %0, {%1, %1};" : "=l"(r) : "f"(x)); return r;
}
__device__ __forceinline__ void fma2(u64 &d, u64 a, u64 b){
    asm("fma.rn.f32x2 %0, %1, %2, %0;" : "+l"(d) : "l"(a), "l"(b));
}
__device__ __forceinline__ float2 unpk(u64 v){
    float2 f; asm("mov.b64 {%0, %1}, %2;" : "=f"(f.x), "=f"(f.y) : "l"(v)); return f;
}
__device__ __forceinline__ float softplusf(float v){
    return fmaxf(v, 0.f) + log1pf(__expf(-fabsf(v)));
}

// ---------------- prep: block0 = bucket, blocks 1..512 = fx/fz GEMMs ---------
__global__ void prep_kernel(const float* __restrict__ x,  const float* __restrict__ W1,
                            const float* __restrict__ b1, const float* __restrict__ W2,
                            const float* __restrict__ b2, const float* __restrict__ z,
                            const float* __restrict__ Wz, const float* __restrict__ bz,
                            const int*   __restrict__ c){
    __shared__ __align__(16) float sbuf[8064];
    __shared__ float aux128[128];
    __shared__ float aux64[64];
    __shared__ int   s_cnt[NCAT];
    __shared__ int   s_cursor[NCAT];
    int tid  = threadIdx.x;
    int lane = tid & 31;

    if (blockIdx.x == 0){
        // ================= bucket sort (warp-aggregated atomics) =============
        if (tid < NCAT) s_cnt[tid] = 0;
        __syncthreads();
        for (int i = tid; i < NN; i += 256){
            int cc = min(max(c[i], 0), NCAT - 1);
            unsigned m = __match_any_sync(0xffffffffu, cc);
            if ((m & ((1u << lane) - 1)) == 0) atomicAdd(&s_cnt[cc], __popc(m));
        }
        __syncthreads();
        if (tid == 0){
            int s = 0, w = 0;
            for (int cc = 0; cc < NCAT; cc++){
                s_cursor[cc] = s;
                g_start[cc]  = s;
                int n = s_cnt[cc];
                g_cnt[cc] = n;
                s += n;
                int nt = (n + 31) >> 5;
                for (int t = 0; t < nt; t++) g_work[w++] = (cc << 16) | t;
            }
            g_nwork = w;
        }
        __syncthreads();
        for (int i = tid; i < NN; i += 256){
            int cc = min(max(c[i], 0), NCAT - 1);
            unsigned m = __match_any_sync(0xffffffffu, cc);
            int leader = __ffs(m) - 1;
            int rank   = __popc(m & ((1u << lane) - 1));
            int base   = 0;
            if (lane == leader) base = atomicAdd(&s_cursor[cc], __popc(m));
            base = __shfl_sync(0xffffffffu, base, leader);
            g_sorted[base + rank] = i;
        }
    } else if (blockIdx.x <= NFX){
        // ================= fx = relu(x@W1+b1)@W2+b2, 32 rows =================
        float* As  = sbuf;            // [32][36]
        float* Bs  = sbuf + 1152;     // [32][64]
        float* Hs  = sbuf;            // [32][52]
        float* W2s = sbuf + 1664;     // [50][128]
        float* b1s = aux64;
        float* b2s = aux128;

        int row0 = (blockIdx.x - 1) * 32;
        if (tid < 64)  b1s[tid] = (tid < HID) ? b1[tid] : 0.f;
        if (tid < 128) b2s[tid] = b2[tid];

        float4 w2r[7];
        #pragma unroll
        for (int i = 0; i < 7; i++){
            int q = tid + 256*i;
            if (q < 1600) w2r[i] = *(const float4*)&W2[q*4];
        }

        int ar = tid >> 3, ac4 = tid & 7;
        float4 pa = *(const float4*)&x[(size_t)(row0 + ar)*INDIM + ac4*4];
        float pb[8];
        #pragma unroll
        for (int i = 0; i < 8; i++){
            int e = tid + 256*i;
            int k = e >> 6, j = e & 63;
            pb[i] = (j < HID) ? W1[(size_t)k*HID + j] : 0.f;
        }

        int rg = (tid >> 4) * 2;
        int cg = (tid & 15) * 4;
        u64 acc2[2][2] = {};

        for (int t = 0; t < 16; t++){
            __syncthreads();
            *(float4*)&As[ar*36 + ac4*4] = pa;
            #pragma unroll
            for (int i = 0; i < 8; i++){
                int e = tid + 256*i;
                Bs[(e >> 6)*64 + (e & 63)] = pb[i];
            }
            __syncthreads();
            if (t < 15){
                int k0 = (t+1)*32;
                pa = *(const float4*)&x[(size_t)(row0 + ar)*INDIM + k0 + ac4*4];
                #pragma unroll
                for (int i = 0; i < 8; i++){
                    int e = tid + 256*i;
                    int k = e >> 6, j = e & 63;
                    pb[i] = (j < HID) ? W1[(size_t)(k0 + k)*HID + j] : 0.f;
                }
            }
            #pragma unroll
            for (int k = 0; k < 32; k++){
                u64 da0 = dup2(As[rg*36 + k]);
                u64 da1 = dup2(As[(rg+1)*36 + k]);
                ulonglong2 bb = *(const ulonglong2*)&Bs[k*64 + cg];
                fma2(acc2[0][0], da0, bb.x); fma2(acc2[0][1], da0, bb.y);
                fma2(acc2[1][0], da1, bb.x); fma2(acc2[1][1], da1, bb.y);
            }
        }
        __syncthreads();

        #pragma unroll
        for (int i = 0; i < 2; i++){
            float2 p0 = unpk(acc2[i][0]);
            float2 p1 = unpk(acc2[i][1]);
            float hv[4] = {p0.x, p0.y, p1.x, p1.y};
            #pragma unroll
            for (int j = 0; j < 4; j++){
                int cc = cg + j;
                if (cc < HID) Hs[(rg+i)*52 + cc] = fmaxf(hv[j] + b1s[cc], 0.f);
            }
        }
        #pragma unroll
        for (int i = 0; i < 7; i++){
            int q = tid + 256*i;
            if (q < 1600) *(float4*)&W2s[q*4] = w2r[i];
        }
        __syncthreads();

        {
            int r0 = (tid >> 5) * 4;
            int c0 = (tid & 31) * 4;
            u64 a2[4][2] = {};
            #pragma unroll
            for (int k = 0; k < HID; k++){
                ulonglong2 bb = *(const ulonglong2*)&W2s[k*128 + c0];
                #pragma unroll
                for (int i = 0; i < 4; i++){
                    u64 da = dup2(Hs[(r0+i)*52 + k]);
                    fma2(a2[i][0], da, bb.x);
                    fma2(a2[i][1], da, bb.y);
                }
            }
            #pragma unroll
            for (int i = 0; i < 4; i++){
                float2 p0 = unpk(a2[i][0]);
                float2 p1 = unpk(a2[i][1]);
                float4 v = make_float4(p0.x + b2s[c0], p0.y + b2s[c0+1],
                                       p1.x + b2s[c0+2], p1.y + b2s[c0+3]);
                *(float4*)&g_fx[(size_t)(row0 + r0 + i)*ZD + c0] = v;
            }
        }
    } else {
        // ================= fz = z@Wz+bz, 32 rows =============================
        float* Zs  = sbuf;            // [32][36]
        float* Wzt = sbuf + 1152;     // [32][132]
        float* bzs = aux128;

        int row0 = (blockIdx.x - 1 - NFX) * 32;
        if (tid < 128) bzs[tid] = bz[tid];

        int ar = tid >> 3, ac4 = tid & 7;
        float4 pz = *(const float4*)&z[(size_t)(row0 + ar)*ZD + ac4*4];
        float4 pw[4];
        #pragma unroll
        for (int i = 0; i < 4; i++){
            int q = tid + 256*i;
            pw[i] = *(const float4*)&Wz[(size_t)(q >> 5)*ZD + (q & 31)*4];
        }

        int rg = (tid >> 4) * 2;
        int cg = (tid & 15) * 4;
        u64 acc2[2][4] = {};

        for (int kt = 0; kt < 4; kt++){
            __syncthreads();
            *(float4*)&Zs[ar*36 + ac4*4] = pz;
            #pragma unroll
            for (int i = 0; i < 4; i++){
                int q = tid + 256*i;
                *(float4*)&Wzt[(q >> 5)*132 + (q & 31)*4] = pw[i];
            }
            __syncthreads();
            if (kt < 3){
                int k0 = (kt+1)*32;
                pz = *(const float4*)&z[(size_t)(row0 + ar)*ZD + k0 + ac4*4];
                #pragma unroll
                for (int i = 0; i < 4; i++){
                    int q = tid + 256*i;
                    pw[i] = *(const float4*)&Wz[(size_t)(k0 + (q >> 5))*ZD + (q & 31)*4];
                }
            }
            #pragma unroll
            for (int k = 0; k < 32; k++){
                u64 da0 = dup2(Zs[rg*36 + k]);
                u64 da1 = dup2(Zs[(rg+1)*36 + k]);
                ulonglong2 b0 = *(const ulonglong2*)&Wzt[k*132 + cg];
                ulonglong2 b1 = *(const ulonglong2*)&Wzt[k*132 + cg + 64];
                fma2(acc2[0][0], da0, b0.x); fma2(acc2[0][1], da0, b0.y);
                fma2(acc2[0][2], da0, b1.x); fma2(acc2[0][3], da0, b1.y);
                fma2(acc2[1][0], da1, b0.x); fma2(acc2[1][1], da1, b0.y);
                fma2(acc2[1][2], da1, b1.x); fma2(acc2[1][3], da1, b1.y);
            }
        }

        #pragma unroll
        for (int i = 0; i < 2; i++){
            size_t base = (size_t)(row0 + rg + i)*ZD;
            float2 p0 = unpk(acc2[i][0]), p1 = unpk(acc2[i][1]);
            float2 p2 = unpk(acc2[i][2]), p3 = unpk(acc2[i][3]);
            *(float4*)&g_fz[base + cg] =
                make_float4(p0.x + bzs[cg],   p0.y + bzs[cg+1],
                            p1.x + bzs[cg+2], p1.y + bzs[cg+3]);
            *(float4*)&g_fz[base + cg + 64] =
                make_float4(p2.x + bzs[cg+64], p2.y + bzs[cg+65],
                            p3.x + bzs[cg+66], p3.y + bzs[cg+67]);
        }
    }
}

// ---------------- fused u + neg + output, 512 threads / work item ------------
// phase1: dup-A FxsTd[k][2r] (pitch 68), Wst[32][132]; 2 rows x 4 cols / thread
// phase2: Us[32][128], Fs[64][132]; 2 rows / warp, 64-wide j-tiles
__global__ void __launch_bounds__(512, 2)
uneg_kernel(const float* __restrict__ Ws, float* __restrict__ out){
    extern __shared__ __align__(16) float dyn[];
    __shared__ float Ts[32];
    __shared__ int   gidx[32];
    float* FxsTd = dyn;          // [128][68]
    float* Wst   = dyn + 8704;   // [32][132]
    float* Us    = dyn;          // [32][128]
    float* Fs    = dyn + 4096;   // [64][132]

    int w = blockIdx.x;
    if (w >= g_nwork) return;
    int item  = g_work[w];
    int cat   = item >> 16, tile = item & 0xffff;
    int start = g_start[cat], cnt = g_cnt[cat];
    int i0    = tile * 32;
    int ni    = min(32, cnt - i0);
    int tid   = threadIdx.x;

    if (tid < 32) gidx[tid] = (tid < ni) ? g_sorted[start + i0 + tid] : 0;

    // stage fx tile transposed + duplicated: 512 threads, 8 k-cols each
    {
        int r  = tid & 31;
        int kg = tid >> 5;                         // 0..15, covers k = kg*8..+7
        int gi = 0; bool act = (r < ni);
        if (act) gi = g_sorted[start + i0 + r];
        const float4* src = (const float4*)&g_fx[(size_t)gi*ZD + kg*8];
        #pragma unroll
        for (int q = 0; q < 2; q++){
            float4 v = act ? src[q] : make_float4(0.f,0.f,0.f,0.f);
            int kb = kg*8 + q*4;
            FxsTd[(kb+0)*68 + 2*r] = v.x; FxsTd[(kb+0)*68 + 2*r + 1] = v.x;
            FxsTd[(kb+1)*68 + 2*r] = v.y; FxsTd[(kb+1)*68 + 2*r + 1] = v.y;
            FxsTd[(kb+2)*68 + 2*r] = v.z; FxsTd[(kb+2)*68 + 2*r + 1] = v.z;
            FxsTd[(kb+3)*68 + 2*r] = v.w; FxsTd[(kb+3)*68 + 2*r + 1] = v.w;
        }
    }

    const float* Wc = Ws + (size_t)cat*ZD*ZD;
    float4 pw[3];
    #pragma unroll
    for (int i = 0; i < 3; i++){
        int q = tid + 512*i;                       // 1056 float4 slots (32x132)
        if (q < 1056){
            int k = q / 33, c4 = q % 33;           // row k, float4-col within padded row
            if (c4 < 32) pw[i] = *(const float4*)&Wc[(size_t)k*ZD + c4*4];
        }
    }

    int r0 = (tid >> 5) * 2;     // warp-uniform: rows r0, r0+1 (0..30)
    int c0 = (tid & 31) * 4;
    u64 acc2[2][2] = {};         // [row][colpair]

    for (int kt = 0; kt < ZD; kt += 32){
        __syncthreads();                          // FxsTd staged (1st) / Wst consumers done
        #pragma unroll
        for (int i = 0; i < 3; i++){
            int q = tid + 512*i;
            if (q < 1056){
                int k = q / 33, c4 = q % 33;
                if (c4 < 32) *(float4*)&Wst[k*132 + c4*4] = pw[i];
            }
        }
        __syncthreads();
        if (kt < ZD - 32){
            #pragma unroll
            for (int i = 0; i < 3; i++){
                int q = tid + 512*i;
                if (q < 1056){
                    int k = q / 33, c4 = q % 33;
                    if (c4 < 32) pw[i] = *(const float4*)&Wc[(size_t)(kt + 32 + k)*ZD + c4*4];
                }
            }
        }
        #pragma unroll
        for (int k = 0; k < 32; k++){
            ulonglong2 a01 = *(const ulonglong2*)&FxsTd[(kt+k)*68 + 2*r0]; // dup(r0), dup(r0+1)
            ulonglong2 bb  = *(const ulonglong2*)&Wst[k*132 + c0];          // colpairs
            fma2(acc2[0][0], a01.x, bb.x); fma2(acc2[0][1], a01.x, bb.y);
            fma2(acc2[1][0], a01.y, bb.x); fma2(acc2[1][1], a01.y, bb.y);
        }
    }
    __syncthreads();             // phase-1 reads done; safe to overwrite

    // write U tile: direct float4 per row
    #pragma unroll
    for (int i = 0; i < 2; i++){
        float2 p0 = unpk(acc2[i][0]);
        float2 p1 = unpk(acc2[i][1]);
        *(float4*)&Us[(r0+i)*128 + c0] = make_float4(p0.x, p0.y, p1.x, p1.y);
    }

    // phase 2: 64-wide j-tiles; warp ig owns rows 2ig, 2ig+1; lane jj covers j0+jj, j0+32+jj
    int jj = tid & 31;
    int ig = tid >> 5;           // 0..15
    float sum[2] = {0.f, 0.f};
    int nt64 = (cnt + 63) >> 6;

    // prefetch first 64-row Fs tile (gathered): 2048 float4 slots / 512 threads
    float4 pf[4];
    {
        int nj0 = min(64, cnt);
        #pragma unroll
        for (int i = 0; i < 4; i++){
            int q = tid + 512*i;
            int r = q >> 5;
            pf[i] = make_float4(0.f,0.f,0.f,0.f);
            if (r < nj0){
                int gj = g_sorted[start + r];
                pf[i] = *(const float4*)&g_fz[(size_t)gj*ZD + (q & 31)*4];
            }
        }
    }

    for (int jt = 0; jt < nt64; jt++){
        int j0 = jt*64;
        int nj = min(64, cnt - j0);
        __syncthreads();         // Us visible (1st) / Fs consumers done
        #pragma unroll
        for (int i = 0; i < 4; i++){
            int q = tid + 512*i;
            *(float4*)&Fs[(q >> 5)*132 + (q & 31)*4] = pf[i];
        }
        __syncthreads();
        if (jt + 1 < nt64){
            int j0n = j0 + 64;
            int njn = min(64, cnt - j0n);
            #pragma unroll
            for (int i = 0; i < 4; i++){
                int q = tid + 512*i;
                int r = q >> 5;
                pf[i] = make_float4(0.f,0.f,0.f,0.f);
                if (r < njn){
                    int gj = g_sorted[start + j0n + r];
                    pf[i] = *(const float4*)&g_fz[(size_t)gj*ZD + (q & 31)*4];
                }
            }
        }

        u64 a1[2] = {}, a2[2] = {};
        #pragma unroll
        for (int k0 = 0; k0 < ZD; k0 += 4){
            ulonglong2 f1 = *(const ulonglong2*)&Fs[jj*132 + k0];
            ulonglong2 f2 = *(const ulonglong2*)&Fs[(jj+32)*132 + k0];
            #pragma unroll
            for (int m = 0; m < 2; m++){
                ulonglong2 u = *(const ulonglong2*)&Us[(2*ig + m)*128 + k0]; // bcast
                fma2(a1[m], u.x, f1.x); fma2(a1[m], u.y, f1.y);
                fma2(a2[m], u.x, f2.x); fma2(a2[m], u.y, f2.y);
            }
        }
        #pragma unroll
        for (int m = 0; m < 2; m++){
            float2 s1 = unpk(a1[m]); float d1 = s1.x + s1.y;
            float2 s2 = unpk(a2[m]); float d2 = s2.x + s2.y;
            int rr = 2*ig + m;
            int gd = i0 + rr;                      // diagonal j within category
            if (rr < ni && gd >= j0 && gd < j0 + 64 && (gd & 31) == jj)
                Ts[rr] = softplusf(((gd - j0) >> 5) ? d2 : d1);
            float v = 0.f;
            if (jj      < nj) v += softplusf(d1);
            if (jj + 32 < nj) v += softplusf(d2);
            v += __shfl_xor_sync(0xffffffffu, v, 16);
            v += __shfl_xor_sync(0xffffffffu, v, 8);
            v += __shfl_xor_sync(0xffffffffu, v, 4);
            v += __shfl_xor_sync(0xffffffffu, v, 2);
            v += __shfl_xor_sync(0xffffffffu, v, 1);
            sum[m] += v;
        }
    }
    __syncthreads();             // Ts visible

    if (jj == 0){
        float inv = 1.f / (float)cnt;
        #pragma unroll
        for (int m = 0; m < 2; m++){
            int rr = 2*ig + m;
            if (rr < ni)
                out[gidx[rr]] = logf(Ts[rr] + EPSV) - logf(sum[m]*inv + EPSV);
        }
    }
}

// ---------------- launch ----------------------------------------------------
extern "C" void kernel_launch(void* const* d_in, const int* in_sizes, int n_in,
                              void* d_out, int out_size){
    const float* x  = (const float*)d_in[0];
    const int*   c  = (const int*)  d_in[1];
    const float* z  = (const float*)d_in[2];
    const float* W1 = (const float*)d_in[3];
    const float* b1 = (const float*)d_in[4];
    const float* W2 = (const float*)d_in[5];
    const float* b2 = (const float*)d_in[6];
    const float* Wz = (const float*)d_in[7];
    const float* bz = (const float*)d_in[8];
    const float* Ws = (const float*)d_in[9];
    float* out = (float*)d_out;

    cudaFuncSetAttribute(uneg_kernel, cudaFuncAttributeMaxDynamicSharedMemorySize,
                         UNEG_SMEM_BYTES);

    prep_kernel <<<1 + NFX + NFZ, 256>>>(x, W1, b1, W2, b2, z, Wz, bz, c);
    uneg_kernel <<<NWORK_MAX, 512, UNEG_SMEM_BYTES>>>(Ws, out);
}

// round 14
// speedup vs baseline: 1.0835x; 1.0835x over previous
#include <cuda_runtime.h>

#define NN 8192
#define INDIM 512
#define HID 50
#define ZD 128
#define NCAT 64
#define EPSV 1e-8f
#define NWORK_MAX (NN/32 + NCAT)
#define NFX2 (NN/64)     // fx blocks (64 rows each)
#define NFZ2 (NN/32)     // fz blocks (32 rows each)

// prep dynamic smem (floats): fz needs zTd[128][68]=8704 + Wzs[128][132]=16896 = 25600
#define PREP_SMEM_FLOATS 25600
#define PREP_SMEM_BYTES  (PREP_SMEM_FLOATS*4)

// uneg dynamic smem layout (floats):
//  phase1: FxsTd [128][68] = 8704   | Wst [32][132] = 4224   (total 12928)
//  phase2: Us    [32][128] = 4096   | Fs  [64][132] = 8448   (total 12544)
#define UNEG_SMEM_FLOATS 12928
#define UNEG_SMEM_BYTES  (UNEG_SMEM_FLOATS*4)

typedef unsigned long long u64;

// ---------------- scratch ----------------------------------------------------
__device__ float g_fx[NN*ZD];    // natural order
__device__ float g_fz[NN*ZD];    // natural order
__device__ int   g_cnt[NCAT], g_start[NCAT];
__device__ int   g_sorted[NN];
__device__ int   g_work[NWORK_MAX];
__device__ int   g_nwork;

// ---------------- f32x2 helpers ----------------------------------------------
__device__ __forceinline__ u64 dup2(float x){
    u64 r; asm("mov.b64 %0, {%1, %1};" : "=l"(r) : "f"(x)); return r;
}
__device__ __forceinline__ void fma2(u64 &d, u64 a, u64 b){
    asm("fma.rn.f32x2 %0, %1, %2, %0;" : "+l"(d) : "l"(a), "l"(b));
}
__device__ __forceinline__ float2 unpk(u64 v){
    float2 f; asm("mov.b64 {%0, %1}, %2;" : "=f"(f.x), "=f"(f.y) : "l"(v)); return f;
}
__device__ __forceinline__ float softplusf(float v){
    return fmaxf(v, 0.f) + log1pf(__expf(-fabsf(v)));
}

// ---------------- prep: block0 = bucket, then fx (64-row) / fz (32-row) ------
__global__ void prep_kernel(const float* __restrict__ x,  const float* __restrict__ W1,
                            const float* __restrict__ b1, const float* __restrict__ W2,
                            const float* __restrict__ b2, const float* __restrict__ z,
                            const float* __restrict__ Wz, const float* __restrict__ bz,
                            const int*   __restrict__ c){
    extern __shared__ __align__(16) float dyn[];
    __shared__ float b1s[64];
    __shared__ float b2s[128];
    __shared__ int   s_cnt[NCAT];
    __shared__ int   s_cursor[NCAT];
    int tid  = threadIdx.x;
    int lane = tid & 31;

    if (blockIdx.x == 0){
        // ================= bucket sort (warp-aggregated atomics) =============
        if (tid < NCAT) s_cnt[tid] = 0;
        __syncthreads();
        for (int i = tid; i < NN; i += 256){
            int cc = min(max(c[i], 0), NCAT - 1);
            unsigned m = __match_any_sync(0xffffffffu, cc);
            if ((m & ((1u << lane) - 1)) == 0) atomicAdd(&s_cnt[cc], __popc(m));
        }
        __syncthreads();
        if (tid == 0){
            int s = 0, w = 0;
            for (int cc = 0; cc < NCAT; cc++){
                s_cursor[cc] = s;
                g_start[cc]  = s;
                int n = s_cnt[cc];
                g_cnt[cc] = n;
                s += n;
                int nt = (n + 31) >> 5;
                for (int t = 0; t < nt; t++) g_work[w++] = (cc << 16) | t;
            }
            g_nwork = w;
        }
        __syncthreads();
        for (int i = tid; i < NN; i += 256){
            int cc = min(max(c[i], 0), NCAT - 1);
            unsigned m = __match_any_sync(0xffffffffu, cc);
            int leader = __ffs(m) - 1;
            int rank   = __popc(m & ((1u << lane) - 1));
            int base   = 0;
            if (lane == leader) base = atomicAdd(&s_cursor[cc], __popc(m));
            base = __shfl_sync(0xffffffffu, base, leader);
            g_sorted[base + rank] = i;
        }
    } else if (blockIdx.x <= NFX2){
        // ===== fx = relu(x@W1+b1)@W2+b2, 64 rows, transposed-A + dup-B =======
        // phase1: AT[32][68] = 2176, Bsd[32][132] = 4224 (dup cols)
        // phase2: HsTd[50][132] = 6600 (dup rows), W2s[50][128] = 6400
        float* AT   = dyn;
        float* Bsd  = dyn + 2176;
        float* HsTd = dyn;
        float* W2s  = dyn + 6600;

        int row0 = (blockIdx.x - 1) * 64;
        if (tid < 64)  b1s[tid] = (tid < HID) ? b1[tid] : 0.f;
        if (tid < 128) b2s[tid] = b2[tid];

        // preload W2 into registers (stored to smem after GEMM1)
        float4 w2r[7];
        #pragma unroll
        for (int i = 0; i < 7; i++){
            int q = tid + 256*i;                 // 1600 float4 slots
            if (q < 1600) w2r[i] = *(const float4*)&W2[q*4];
        }

        // GEMM1 prefetch: A 64x32 = 512 float4 (2/thread), B 32x64 = 2048 scalars (8/thread)
        float4 pa[2];
        #pragma unroll
        for (int i = 0; i < 2; i++){
            int s = tid + 256*i;
            pa[i] = *(const float4*)&x[(size_t)(row0 + (s >> 3))*INDIM + (s & 7)*4];
        }
        float pb[8];
        #pragma unroll
        for (int i = 0; i < 8; i++){
            int e = tid + 256*i;
            int k = e >> 6, j = e & 63;
            pb[i] = (j < HID) ? W1[(size_t)k*HID + j] : 0.f;
        }

        int r0 = (tid >> 5) * 8;     // warp-uniform: rows r0..r0+7
        int c0 = (tid & 31) * 2;     // lane cols c0, c0+1
        u64 acc[4][2] = {};          // [rowpair p = rows r0+2p,r0+2p+1][col j]

        for (int t = 0; t < 16; t++){
            __syncthreads();
            #pragma unroll
            for (int i = 0; i < 2; i++){
                int s = tid + 256*i;
                int r = s >> 3, kq = s & 7;
                float4 v = pa[i];
                AT[(kq*4+0)*68 + r] = v.x;
                AT[(kq*4+1)*68 + r] = v.y;
                AT[(kq*4+2)*68 + r] = v.z;
                AT[(kq*4+3)*68 + r] = v.w;
            }
            #pragma unroll
            for (int i = 0; i < 8; i++){
                int e = tid + 256*i;
                int k = e >> 6, j = e & 63;
                Bsd[k*132 + 2*j]     = pb[i];
                Bsd[k*132 + 2*j + 1] = pb[i];
            }
            __syncthreads();
            if (t < 15){
                int k0 = (t+1)*32;
                #pragma unroll
                for (int i = 0; i < 2; i++){
                    int s = tid + 256*i;
                    pa[i] = *(const float4*)&x[(size_t)(row0 + (s >> 3))*INDIM + k0 + (s & 7)*4];
                }
                #pragma unroll
                for (int i = 0; i < 8; i++){
                    int e = tid + 256*i;
                    int k = e >> 6, j = e & 63;
                    pb[i] = (j < HID) ? W1[(size_t)(k0 + k)*HID + j] : 0.f;
                }
            }
            #pragma unroll
            for (int k = 0; k < 32; k++){
                ulonglong2 a03 = *(const ulonglong2*)&AT[k*68 + r0];      // rowpairs 0,1
                ulonglong2 a47 = *(const ulonglong2*)&AT[k*68 + r0 + 4];  // rowpairs 2,3
                ulonglong2 bd  = *(const ulonglong2*)&Bsd[k*132 + 2*c0];  // dup(c0), dup(c0+1)
                fma2(acc[0][0], a03.x, bd.x); fma2(acc[0][1], a03.x, bd.y);
                fma2(acc[1][0], a03.y, bd.x); fma2(acc[1][1], a03.y, bd.y);
                fma2(acc[2][0], a47.x, bd.x); fma2(acc[2][1], a47.x, bd.y);
                fma2(acc[3][0], a47.y, bd.x); fma2(acc[3][1], a47.y, bd.y);
            }
        }
        __syncthreads();             // GEMM1 smem reads done

        // hidden (ReLU+bias) -> HsTd (transposed, duplicated rows)
        #pragma unroll
        for (int p = 0; p < 4; p++){
            #pragma unroll
            for (int j = 0; j < 2; j++){
                int cc = c0 + j;
                if (cc < HID){
                    float2 v = unpk(acc[p][j]);          // rows r0+2p, r0+2p+1
                    float h0 = fmaxf(v.x + b1s[cc], 0.f);
                    float h1 = fmaxf(v.y + b1s[cc], 0.f);
                    int rA = r0 + 2*p;
                    HsTd[cc*132 + 2*rA]     = h0;
                    HsTd[cc*132 + 2*rA + 1] = h0;
                    HsTd[cc*132 + 2*rA + 2] = h1;
                    HsTd[cc*132 + 2*rA + 3] = h1;
                }
            }
        }
        #pragma unroll
        for (int i = 0; i < 7; i++){
            int q = tid + 256*i;
            if (q < 1600) *(float4*)&W2s[q*4] = w2r[i];
        }
        __syncthreads();

        // GEMM2: 64x128, K=50; 8 rows x 4 cols per thread
        {
            int c2 = (tid & 31) * 4;
            u64 a2[8][2] = {};       // [row][colpair]
            #pragma unroll
            for (int h = 0; h < HID; h++){
                const float* hp = &HsTd[h*132 + 2*r0];
                ulonglong2 A0 = *(const ulonglong2*)hp;          // dup r0, r0+1
                ulonglong2 A1 = *(const ulonglong2*)(hp + 4);    // dup r0+2, r0+3
                ulonglong2 A2 = *(const ulonglong2*)(hp + 8);
                ulonglong2 A3 = *(const ulonglong2*)(hp + 12);
                ulonglong2 B  = *(const ulonglong2*)&W2s[h*128 + c2];
                fma2(a2[0][0], A0.x, B.x); fma2(a2[0][1], A0.x, B.y);
                fma2(a2[1][0], A0.y, B.x); fma2(a2[1][1], A0.y, B.y);
                fma2(a2[2][0], A1.x, B.x); fma2(a2[2][1], A1.x, B.y);
                fma2(a2[3][0], A1.y, B.x); fma2(a2[3][1], A1.y, B.y);
                fma2(a2[4][0], A2.x, B.x); fma2(a2[4][1], A2.x, B.y);
                fma2(a2[5][0], A2.y, B.x); fma2(a2[5][1], A2.y, B.y);
                fma2(a2[6][0], A3.x, B.x); fma2(a2[6][1], A3.x, B.y);
                fma2(a2[7][0], A3.y, B.x); fma2(a2[7][1], A3.y, B.y);
            }
            #pragma unroll
            for (int i = 0; i < 8; i++){
                float2 p0 = unpk(a2[i][0]);
                float2 p1 = unpk(a2[i][1]);
                float4 v = make_float4(p0.x + b2s[c2], p0.y + b2s[c2+1],
                                       p1.x + b2s[c2+2], p1.y + b2s[c2+3]);
                *(float4*)&g_fx[(size_t)(row0 + r0 + i)*ZD + c2] = v;
            }
        }
    } else {
        // ===== fz = z@Wz+bz, 32 rows, FULL Wz resident, no in-loop syncs =====
        // zTd[128][68] (k x dup-rows), Wzs[128][132]
        float* zTd = dyn;
        float* Wzs = dyn + 8704;

        int row0 = (blockIdx.x - 1 - NFX2) * 32;

        // stage z tile transposed+dup: 1024 float4 slots (4/thread)
        #pragma unroll
        for (int i = 0; i < 4; i++){
            int s = tid + 256*i;
            int r = s >> 5, kq = s & 31;
            float4 v = *(const float4*)&z[(size_t)(row0 + r)*ZD + kq*4];
            zTd[(kq*4+0)*68 + 2*r] = v.x; zTd[(kq*4+0)*68 + 2*r + 1] = v.x;
            zTd[(kq*4+1)*68 + 2*r] = v.y; zTd[(kq*4+1)*68 + 2*r + 1] = v.y;
            zTd[(kq*4+2)*68 + 2*r] = v.z; zTd[(kq*4+2)*68 + 2*r + 1] = v.z;
            zTd[(kq*4+3)*68 + 2*r] = v.w; zTd[(kq*4+3)*68 + 2*r + 1] = v.w;
        }
        // stage full Wz: 4096 float4 slots (16/thread)
        #pragma unroll
        for (int i = 0; i < 16; i++){
            int q = tid + 256*i;
            int k = q >> 5, c4 = q & 31;
            *(float4*)&Wzs[k*132 + c4*4] = *(const float4*)&Wz[(size_t)k*ZD + c4*4];
        }
        __syncthreads();

        int rg = (tid >> 5) * 4;     // warp-uniform rows rg..rg+3
        int cg = (tid & 31) * 4;
        u64 acc[4][2] = {};          // [row][colpair]

        #pragma unroll 4
        for (int k = 0; k < ZD; k++){
            const float* ap = &zTd[k*68 + 2*rg];
            ulonglong2 a01 = *(const ulonglong2*)ap;        // dup(rg), dup(rg+1)
            ulonglong2 a23 = *(const ulonglong2*)(ap + 4);  // dup(rg+2), dup(rg+3)
            ulonglong2 bb  = *(const ulonglong2*)&Wzs[k*132 + cg];
            fma2(acc[0][0], a01.x, bb.x); fma2(acc[0][1], a01.x, bb.y);
            fma2(acc[1][0], a01.y, bb.x); fma2(acc[1][1], a01.y, bb.y);
            fma2(acc[2][0], a23.x, bb.x); fma2(acc[2][1], a23.x, bb.y);
            fma2(acc[3][0], a23.y, bb.x); fma2(acc[3][1], a23.y, bb.y);
        }

        float4 bzv = *(const float4*)&bz[cg];
        #pragma unroll
        for (int i = 0; i < 4; i++){
            float2 p0 = unpk(acc[i][0]);
            float2 p1 = unpk(acc[i][1]);
            float4 v = make_float4(p0.x + bzv.x, p0.y + bzv.y,
                                   p1.x + bzv.z, p1.y + bzv.w);
            *(float4*)&g_fz[(size_t)(row0 + rg + i)*ZD + cg] = v;
        }
    }
}

// ---------------- fused u + neg + output, 32-row i-tiles (R12, proven) -------
__global__ void __launch_bounds__(256)
uneg_kernel(const float* __restrict__ Ws, float* __restrict__ out){
    extern __shared__ __align__(16) float dyn[];
    __shared__ float Ts[32];
    __shared__ int   gidx[32];
    float* FxsTd = dyn;          // [128][68]
    float* Wst   = dyn + 8704;   // [32][132]
    float* Us    = dyn;          // [32][128]
    float* Fs    = dyn + 4096;   // [64][132]

    int w = blockIdx.x;
    if (w >= g_nwork) return;
    int item  = g_work[w];
    int cat   = item >> 16, tile = item & 0xffff;
    int start = g_start[cat], cnt = g_cnt[cat];
    int i0    = tile * 32;
    int ni    = min(32, cnt - i0);
    int tid   = threadIdx.x;

    if (tid < 32) gidx[tid] = (tid < ni) ? g_sorted[start + i0 + tid] : 0;

    // stage fx tile transposed + DUPLICATED: FxsTd[k][2r] = FxsTd[k][2r+1] = fx
    {
        int r = tid & 31, kg = tid >> 5;          // kg: 16-k chunk
        int gi = 0; bool act = (r < ni);
        if (act) gi = g_sorted[start + i0 + r];
        const float4* src = (const float4*)&g_fx[(size_t)gi*ZD + kg*16];
        #pragma unroll
        for (int q = 0; q < 4; q++){
            float4 v = act ? src[q] : make_float4(0.f,0.f,0.f,0.f);
            int kb = kg*16 + q*4;
            FxsTd[(kb+0)*68 + 2*r] = v.x; FxsTd[(kb+0)*68 + 2*r + 1] = v.x;
            FxsTd[(kb+1)*68 + 2*r] = v.y; FxsTd[(kb+1)*68 + 2*r + 1] = v.y;
            FxsTd[(kb+2)*68 + 2*r] = v.z; FxsTd[(kb+2)*68 + 2*r + 1] = v.z;
            FxsTd[(kb+3)*68 + 2*r] = v.w; FxsTd[(kb+3)*68 + 2*r + 1] = v.w;
        }
    }

    const float* Wc = Ws + (size_t)cat*ZD*ZD;
    float4 pw[4];
    #pragma unroll
    for (int i = 0; i < 4; i++){
        int q = tid + 256*i;
        pw[i] = *(const float4*)&Wc[(size_t)(q >> 5)*ZD + (q & 31)*4];
    }
    // prefetch first 64-row Fs tile (gathered)
    float4 pf[8];
    {
        int nj0 = min(64, cnt);
        #pragma unroll
        for (int i = 0; i < 8; i++){
            int q = tid + 256*i;                   // 2048 slots: 64 rows x 32 float4
            int r = q >> 5;
            pf[i] = make_float4(0.f,0.f,0.f,0.f);
            if (r < nj0){
                int gj = g_sorted[start + r];
                pf[i] = *(const float4*)&g_fz[(size_t)gj*ZD + (q & 31)*4];
            }
        }
    }

    int r0 = (tid >> 5) * 4;     // warp-uniform row group
    int c0 = (tid & 31) * 4;
    u64 acc2[4][2] = {};         // [row][colpair]

    for (int kt = 0; kt < ZD; kt += 32){
        __syncthreads();                          // FxsTd staged (1st) / Wst consumers done
        #pragma unroll
        for (int i = 0; i < 4; i++){
            int q = tid + 256*i;
            *(float4*)&Wst[(q >> 5)*132 + (q & 31)*4] = pw[i];
        }
        __syncthreads();
        if (kt < ZD - 32){
            #pragma unroll
            for (int i = 0; i < 4; i++){
                int q = tid + 256*i;
                pw[i] = *(const float4*)&Wc[(size_t)(kt + 32 + (q >> 5))*ZD + (q & 31)*4];
            }
        }
        #pragma unroll
        for (int k = 0; k < 32; k++){
            const float* ap = &FxsTd[(kt+k)*68 + 2*r0];
            ulonglong2 a01 = *(const ulonglong2*)ap;        // dup(r0), dup(r0+1)
            ulonglong2 a23 = *(const ulonglong2*)(ap + 4);  // dup(r0+2), dup(r0+3)
            ulonglong2 bb  = *(const ulonglong2*)&Wst[k*132 + c0];  // colpairs
            fma2(acc2[0][0], a01.x, bb.x); fma2(acc2[0][1], a01.x, bb.y);
            fma2(acc2[1][0], a01.y, bb.x); fma2(acc2[1][1], a01.y, bb.y);
            fma2(acc2[2][0], a23.x, bb.x); fma2(acc2[2][1], a23.x, bb.y);
            fma2(acc2[3][0], a23.y, bb.x); fma2(acc2[3][1], a23.y, bb.y);
        }
    }
    __syncthreads();             // phase-1 reads done; safe to overwrite

    // write U tile: acc[row] pairs are (c0,c0+1),(c0+2,c0+3) -> direct float4
    #pragma unroll
    for (int i = 0; i < 4; i++){
        float2 p0 = unpk(acc2[i][0]);
        float2 p1 = unpk(acc2[i][1]);
        *(float4*)&Us[(r0+i)*128 + c0] = make_float4(p0.x, p0.y, p1.x, p1.y);
    }

    // phase 2: 64-wide j-tiles; lane jj handles j = j0+jj and j0+32+jj
    int jj = tid & 31;
    int ig = tid >> 5;           // warp owns rows ig*4..+3
    float sum[4] = {0.f, 0.f, 0.f, 0.f};
    int nt64 = (cnt + 63) >> 6;

    for (int jt = 0; jt < nt64; jt++){
        int j0 = jt*64;
        int nj = min(64, cnt - j0);
        __syncthreads();         // Us visible (1st) / Fs consumers done
        #pragma unroll
        for (int i = 0; i < 8; i++){
            int q = tid + 256*i;
            *(float4*)&Fs[(q >> 5)*132 + (q & 31)*4] = pf[i];
        }
        __syncthreads();
        if (jt + 1 < nt64){
            int j0n = j0 + 64;
            int njn = min(64, cnt - j0n);
            #pragma unroll
            for (int i = 0; i < 8; i++){
                int q = tid + 256*i;
                int r = q >> 5;
                pf[i] = make_float4(0.f,0.f,0.f,0.f);
                if (r < njn){
                    int gj = g_sorted[start + j0n + r];
                    pf[i] = *(const float4*)&g_fz[(size_t)gj*ZD + (q & 31)*4];
                }
            }
        }

        u64 a1[4] = {}, a2[4] = {};
        #pragma unroll
        for (int k0 = 0; k0 < ZD; k0 += 4){
            ulonglong2 f1 = *(const ulonglong2*)&Fs[jj*132 + k0];
            ulonglong2 f2 = *(const ulonglong2*)&Fs[(jj+32)*132 + k0];
            #pragma unroll
            for (int m = 0; m < 4; m++){
                ulonglong2 u = *(const ulonglong2*)&Us[(ig*4 + m)*128 + k0]; // bcast
                fma2(a1[m], u.x, f1.x); fma2(a1[m], u.y, f1.y);
                fma2(a2[m], u.x, f2.x); fma2(a2[m], u.y, f2.y);
            }
        }
        #pragma unroll
        for (int m = 0; m < 4; m++){
            float2 s1 = unpk(a1[m]); float d1 = s1.x + s1.y;
            float2 s2 = unpk(a2[m]); float d2 = s2.x + s2.y;
            int rr = ig*4 + m;
            int gd = i0 + rr;                      // diagonal j within category
            if (rr < ni && gd >= j0 && gd < j0 + 64 && (gd & 31) == jj)
                Ts[rr] = softplusf(((gd - j0) >> 5) ? d2 : d1);
            float v = 0.f;
            if (jj      < nj) v += softplusf(d1);
            if (jj + 32 < nj) v += softplusf(d2);
            v += __shfl_xor_sync(0xffffffffu, v, 16);
            v += __shfl_xor_sync(0xffffffffu, v, 8);
            v += __shfl_xor_sync(0xffffffffu, v, 4);
            v += __shfl_xor_sync(0xffffffffu, v, 2);
            v += __shfl_xor_sync(0xffffffffu, v, 1);
            sum[m] += v;
        }
    }
    __syncthreads();             // Ts visible

    if (jj == 0){
        float inv = 1.f / (float)cnt;
        #pragma unroll
        for (int m = 0; m < 4; m++){
            int rr = ig*4 + m;
            if (rr < ni)
                out[gidx[rr]] = logf(Ts[rr] + EPSV) - logf(sum[m]*inv + EPSV);
        }
    }
}

// ---------------- launch ----------------------------------------------------
extern "C" void kernel_launch(void* const* d_in, const int* in_sizes, int n_in,
                              void* d_out, int out_size){
    const float* x  = (const float*)d_in[0];
    const int*   c  = (const int*)  d_in[1];
    const float* z  = (const float*)d_in[2];
    const float* W1 = (const float*)d_in[3];
    const float* b1 = (const float*)d_in[4];
    const float* W2 = (const float*)d_in[5];
    const float* b2 = (const float*)d_in[6];
    const float* Wz = (const float*)d_in[7];
    const float* bz = (const float*)d_in[8];
    const float* Ws = (const float*)d_in[9];
    float* out = (float*)d_out;

    cudaFuncSetAttribute(prep_kernel, cudaFuncAttributeMaxDynamicSharedMemorySize,
                         PREP_SMEM_BYTES);
    cudaFuncSetAttribute(uneg_kernel, cudaFuncAttributeMaxDynamicSharedMemorySize,
                         UNEG_SMEM_BYTES);

    prep_kernel <<<1 + NFX2 + NFZ2, 256, PREP_SMEM_BYTES>>>(x, W1, b1, W2, b2, z, Wz, bz, c);
    uneg_kernel <<<NWORK_MAX, 256, UNEG_SMEM_BYTES>>>(Ws, out);
}